// round 8
// baseline (speedup 1.0000x reference)
#include <cuda_runtime.h>
#include <cuda_bf16.h>
#include <cuda_fp16.h>
#include <math.h>

#define IN_DIM 256
#define H_DIM 64
#define OUT_DIM 16
#define MAXN 50000
#define MAXE 800000
#define CSR_CAP 128
#define FAGCN_EPS 0.3f

// ---------------- scratch (no allocation allowed) ----------------
__device__ float  g_raw[MAXN * H_DIM];
__device__ __half g_raw16[MAXN * H_DIM];
__device__ __half g_x1h[MAXN * H_DIM];
__device__ float  g_x2[MAXN * H_DIM];
__device__ int    g_cnt[MAXN];
__device__ int    g_csr[MAXN * CSR_CAP];
__device__ float  g_a1[MAXN];
__device__ float2 g_cd1[MAXN];
__device__ float  g_a2[MAXN];
__device__ float2 g_cd2[MAXN];

__device__ __forceinline__ float tanh_approx(float x) {
    float r;
    asm("tanh.approx.f32 %0, %1;" : "=f"(r) : "f"(x));
    return r;
}

// ---------------- CSR build ----------------
__global__ void k_zero(int* __restrict__ p, int n) {
    int i = blockIdx.x * blockDim.x + threadIdx.x;
    if (i < n) p[i] = 0;
}

__global__ void k_fill(const int* __restrict__ src, const int* __restrict__ dst,
                       int* __restrict__ cnt, int* __restrict__ csr,
                       int e0, int e1) {
    int i = e0 + blockIdx.x * blockDim.x + threadIdx.x;
    if (i < e1) {
        int t = dst[i];
        int pos = atomicAdd(&cnt[t], 1);
        if (pos < CSR_CAP) csr[t * CSR_CAP + pos] = src[i];
    }
}

// ---------------- t1: 8x4 register-tiled GEMM, 256 thr, 4 blocks/SM ----------------
// Block computes 128 nodes x 64 outs. Thread tile = 8 nodes x 4 outs (32 acc regs).
// 16 out-groups x 16 node-groups. W staged in four 64-k transposed phases.
#define T1_BM 128
#define T1_WROW 68   // padded row for wT[64][68] (one 64-k phase)
#define T1_HROW 36   // padded row for hS[128][36]
#define T1_SMEM ((64 * T1_WROW + T1_BM * T1_HROW) * 4)

__global__ void __launch_bounds__(256, 4)
k_t1(const float* __restrict__ hin, const float* __restrict__ w,
     const float* __restrict__ b, float* __restrict__ out,
     __half* __restrict__ out16, int N) {
    extern __shared__ float sm[];
    float* wT = sm;                  // [64 k][68] current phase, transposed
    float* hS = sm + 64 * T1_WROW;   // [128 nodes][36]
    int tx = threadIdx.x;
    int jg = tx & 15;                // out-group (4 outs)
    int mg = tx >> 4;                // node-group (8 nodes)

    int n0 = blockIdx.x * T1_BM;
    float acc[8][4];
#pragma unroll
    for (int r = 0; r < 8; r++)
#pragma unroll
        for (int c = 0; c < 4; c++) acc[r][c] = 0.0f;

    const float4* w4 = (const float4*)w;   // 64 rows x 64 float4

    for (int ph = 0; ph < 4; ph++) {
        __syncthreads();   // protect wT reuse across phases
        // stage + transpose 64 k-columns of W: j=0..63, k4l=0..15 (1024 float4)
#pragma unroll
        for (int i = 0; i < 4; i++) {
            int idx = tx + i * 256;   // 0..1023
            int j   = idx >> 4;       // 0..63
            int k4l = idx & 15;       // 0..15
            float4 v = w4[j * 64 + ph * 16 + k4l];
            wT[(k4l * 4 + 0) * T1_WROW + j] = v.x;
            wT[(k4l * 4 + 1) * T1_WROW + j] = v.y;
            wT[(k4l * 4 + 2) * T1_WROW + j] = v.z;
            wT[(k4l * 4 + 3) * T1_WROW + j] = v.w;
        }

        for (int kt = 0; kt < 2; kt++) {
            int kb = ph * 64 + kt * 32;
            __syncthreads();
            // stage hS: 128 nodes x 32 k (1024 float4, 4 per thread)
#pragma unroll
            for (int i = 0; i < 4; i++) {
                int idx = tx + i * 256;
                int nl = idx >> 3;
                int k4 = idx & 7;
                int n  = n0 + nl;
                float4 v;
                if (n < N) v = *(const float4*)(hin + (size_t)n * IN_DIM + kb + k4 * 4);
                else       v = make_float4(0.f, 0.f, 0.f, 0.f);
                *(float4*)(hS + nl * T1_HROW + k4 * 4) = v;
            }
            __syncthreads();
#pragma unroll
            for (int k = 0; k < 32; k++) {
                int kl = kt * 32 + k;   // 0..63 within phase
                float4 wv = *(const float4*)(wT + kl * T1_WROW + jg * 4);
                const float* hp = hS + (mg * 8) * T1_HROW + k;
#pragma unroll
                for (int r = 0; r < 8; r++) {
                    float hv = hp[r * T1_HROW];
                    acc[r][0] += hv * wv.x;
                    acc[r][1] += hv * wv.y;
                    acc[r][2] += hv * wv.z;
                    acc[r][3] += hv * wv.w;
                }
            }
        }
    }

    float4 bj = *(const float4*)(b + jg * 4);
#pragma unroll
    for (int r = 0; r < 8; r++) {
        int n = n0 + mg * 8 + r;
        if (n < N) {
            float4 o;
            o.x = fmaxf(acc[r][0] + bj.x, 0.f);
            o.y = fmaxf(acc[r][1] + bj.y, 0.f);
            o.z = fmaxf(acc[r][2] + bj.z, 0.f);
            o.w = fmaxf(acc[r][3] + bj.w, 0.f);
            *(float4*)(out + (size_t)n * H_DIM + jg * 4) = o;
            __half2 h0 = __floats2half2_rn(o.x, o.y);
            __half2 h1 = __floats2half2_rn(o.z, o.w);
            uint2 u;
            u.x = *(unsigned*)&h0; u.y = *(unsigned*)&h1;
            *(uint2*)(out16 + (size_t)n * H_DIM + jg * 4) = u;
        }
    }
}

// ---------------- per-node gate precompute (+ degree norm) ----------------
__global__ void __launch_bounds__(256)
k_gate(const float* __restrict__ x, const float* __restrict__ gw,
       const int* __restrict__ cnt, float* __restrict__ a,
       float2* __restrict__ cd, int N) {
    int warp = (blockIdx.x * blockDim.x + threadIdx.x) >> 5;
    int lane = threadIdx.x & 31;
    if (warp >= N) return;
    float2 xv = *(const float2*)(x + (size_t)warp * 64 + lane * 2);
    float2 wa = *(const float2*)(gw + lane * 2);
    float2 wc = *(const float2*)(gw + 64 + lane * 2);
    float pa = xv.x * wa.x + xv.y * wa.y;
    float pc = xv.x * wc.x + xv.y * wc.y;
#pragma unroll
    for (int o = 16; o; o >>= 1) {
        pa += __shfl_xor_sync(0xffffffffu, pa, o);
        pc += __shfl_xor_sync(0xffffffffu, pc, o);
    }
    if (lane == 0) {
        a[warp] = pa;
        float d = rsqrtf(fmaxf((float)cnt[warp], 1.0f));
        cd[warp] = make_float2(pc, d);
    }
}

// ---------------- aggregation: HFMA2 batches, 2 nodes/warp ----------------
__global__ void __launch_bounds__(256)
k_aggr(const __half* __restrict__ x, const float* __restrict__ raw,
       float* __restrict__ xn_f, __half* __restrict__ xn_h,
       const int* __restrict__ csr, const int* __restrict__ cnt,
       const float* __restrict__ a, const float2* __restrict__ cd,
       const float* __restrict__ gbp, int layer,
       const float* __restrict__ gw_next, float* __restrict__ a_next,
       float2* __restrict__ cd_next,
       int N, int fuse) {
    int warp = (blockIdx.x * blockDim.x + threadIdx.x) >> 5;
    int lane = threadIdx.x & 31;
    int half = lane >> 4;
    int l = lane & 15;

    int t = warp * 2 + half;
    bool nvalid = (t < N);
    int tc = nvalid ? t : 0;

    int deg = nvalid ? min(cnt[tc], CSR_CAP) : 0;
    int start = tc * CSR_CAP;
    float2 cdt = cd[tc];
    float base = a[tc] + gbp[layer];
    float dt = cdt.y;

    int deg_o = __shfl_xor_sync(0xffffffffu, deg, 16);
    int degmax = max(deg, deg_o);

    float4 rv = nvalid ? *(const float4*)(raw + (size_t)t * 64 + l * 4)
                       : make_float4(0.f, 0.f, 0.f, 0.f);
    float4 acc;
    acc.x = FAGCN_EPS * rv.x;
    acc.y = FAGCN_EPS * rv.y;
    acc.z = FAGCN_EPS * rv.z;
    acc.w = FAGCN_EPS * rv.w;

    for (int b0 = 0; b0 < degmax; b0 += 16) {
        int ei = b0 + l;
        int sb = 0;
        unsigned ep = 0;
        if (ei < deg) {
            sb = csr[start + ei];
            float2 cs = cd[sb];
            float ev = tanh_approx(base + cs.x) * dt * cs.y;
            __half2 e2 = __float2half2_rn(ev);
            ep = *(unsigned*)&e2;
        }
        int mmax = min(16, degmax - b0);
        __half2 hacc0 = __float2half2_rn(0.0f);
        __half2 hacc1 = hacc0;
        if (mmax == 16) {
#pragma unroll
            for (int bq = 0; bq < 16; bq++) {
                int srcl = (lane & 16) | bq;
                unsigned e = __shfl_sync(0xffffffffu, ep, srcl);
                int s  = __shfl_sync(0xffffffffu, sb, srcl);
                uint2 u = *(const uint2*)(x + (size_t)s * 64 + l * 4);
                hacc0 = __hfma2(*(__half2*)&u.x, *(__half2*)&e, hacc0);
                hacc1 = __hfma2(*(__half2*)&u.y, *(__half2*)&e, hacc1);
            }
        } else {
            for (int bq = 0; bq < mmax; bq++) {
                int srcl = (lane & 16) | bq;
                unsigned e = __shfl_sync(0xffffffffu, ep, srcl);
                int s  = __shfl_sync(0xffffffffu, sb, srcl);
                uint2 u = *(const uint2*)(x + (size_t)s * 64 + l * 4);
                hacc0 = __hfma2(*(__half2*)&u.x, *(__half2*)&e, hacc0);
                hacc1 = __hfma2(*(__half2*)&u.y, *(__half2*)&e, hacc1);
            }
        }
        float2 f0 = __half22float2(hacc0);
        float2 f1 = __half22float2(hacc1);
        acc.x += f0.x;
        acc.y += f0.y;
        acc.z += f1.x;
        acc.w += f1.y;
    }

    if (nvalid) {
        if (xn_f)
            *(float4*)(xn_f + (size_t)t * 64 + l * 4) = acc;
        if (xn_h) {
            __half2 h0 = __floats2half2_rn(acc.x, acc.y);
            __half2 h1 = __floats2half2_rn(acc.z, acc.w);
            uint2 u;
            u.x = *(unsigned*)&h0;
            u.y = *(unsigned*)&h1;
            *(uint2*)(xn_h + (size_t)t * 64 + l * 4) = u;
        }
    }

    if (fuse && nvalid) {
        float4 wa = *(const float4*)(gw_next + l * 4);
        float4 wc = *(const float4*)(gw_next + 64 + l * 4);
        float pa = acc.x * wa.x + acc.y * wa.y + acc.z * wa.z + acc.w * wa.w;
        float pc = acc.x * wc.x + acc.y * wc.y + acc.z * wc.z + acc.w * wc.w;
#pragma unroll
        for (int o = 8; o; o >>= 1) {
            pa += __shfl_xor_sync(0xffffffffu, pa, o);
            pc += __shfl_xor_sync(0xffffffffu, pc, o);
        }
        if (l == 0) {
            a_next[t] = pa;
            cd_next[t] = make_float2(pc, dt);
        }
    }
}

// ---------------- output ----------------
__global__ void k_out(const float* __restrict__ x, const float* __restrict__ w2,
                      const float* __restrict__ b2, float* __restrict__ out, int N) {
    __shared__ float wS[16 * 64];
    __shared__ float xS[8][64];
    int t = threadIdx.x;
    for (int idx = t; idx < 16 * 64; idx += 128) wS[idx] = w2[idx];

    int node = blockIdx.x * 8 + (t >> 4);
    int j = t & 15;
    bool valid = (node < N);
    int nc = valid ? node : (N - 1);

    __syncthreads();
    {
        const float4* xp = (const float4*)(x + (size_t)nc * 64);
        ((float4*)xS[t >> 4])[j] = xp[j];
    }
    __syncthreads();

    const float4* xr = (const float4*)xS[t >> 4];
    const float4* wr = (const float4*)(wS + j * 64);
    float acc = b2[j];
#pragma unroll
    for (int k = 0; k < 16; k++) {
        float4 av = xr[k];
        float4 wv = wr[k];
        acc += av.x * wv.x + av.y * wv.y + av.z * wv.z + av.w * wv.w;
    }
    float m = acc;
    for (int o = 8; o; o >>= 1) m = fmaxf(m, __shfl_xor_sync(0xffffffffu, m, o));
    float ex = expf(acc - m);
    float s = ex;
    for (int o = 8; o; o >>= 1) s += __shfl_xor_sync(0xffffffffu, s, o);
    if (valid) out[(size_t)node * 16 + j] = acc - m - logf(s);
}

// ---------------- launch ----------------
extern "C" void kernel_launch(void* const* d_in, const int* in_sizes, int n_in,
                              void* d_out, int out_size) {
    const float* h   = (const float*)d_in[0];
    const int*   src = (const int*)  d_in[1];
    const int*   dst = (const int*)  d_in[2];
    const float* t1w = (const float*)d_in[3];
    const float* t1b = (const float*)d_in[4];
    const float* gw  = (const float*)d_in[5];
    const float* gb  = (const float*)d_in[6];
    const float* t2w = (const float*)d_in[7];
    const float* t2b = (const float*)d_in[8];
    float* out = (float*)d_out;

    int N = in_sizes[0] / IN_DIM;
    int E = in_sizes[1];

    float *raw, *x2, *a1, *a2;
    __half *raw16, *x1h;
    float2 *cd1, *cd2;
    int *cnt, *csr;
    cudaGetSymbolAddress((void**)&raw,   g_raw);
    cudaGetSymbolAddress((void**)&raw16, g_raw16);
    cudaGetSymbolAddress((void**)&x1h,   g_x1h);
    cudaGetSymbolAddress((void**)&x2,    g_x2);
    cudaGetSymbolAddress((void**)&cnt,   g_cnt);
    cudaGetSymbolAddress((void**)&csr,   g_csr);
    cudaGetSymbolAddress((void**)&a1,    g_a1);
    cudaGetSymbolAddress((void**)&a2,    g_a2);
    cudaGetSymbolAddress((void**)&cd1,   g_cd1);
    cudaGetSymbolAddress((void**)&cd2,   g_cd2);

    // kernel order: zero(1), fill_a(2), fill_b(3), t1(4 <- ncu capture slot),
    // gate(5), aggr0(6), aggr1(7), out(8)
    k_zero<<<(N + 255) / 256, 256>>>(cnt, N);
    int Eh = E / 2;
    k_fill<<<(Eh + 255) / 256, 256>>>(src, dst, cnt, csr, 0, Eh);
    k_fill<<<(E - Eh + 255) / 256, 256>>>(src, dst, cnt, csr, Eh, E);

    cudaFuncSetAttribute(k_t1, cudaFuncAttributeMaxDynamicSharedMemorySize, T1_SMEM);
    k_t1<<<(N + T1_BM - 1) / T1_BM, 256, T1_SMEM>>>(h, t1w, t1b, raw, raw16, N);

    int gblk = (N * 32 + 255) / 256;
    k_gate<<<gblk, 256>>>(raw, gw, cnt, a1, cd1, N);

    int ablk = (N + 15) / 16;
    k_aggr<<<ablk, 256>>>(raw16, raw, nullptr, x1h, csr, cnt, a1, cd1, gb, 0,
                          gw + 128, a2, cd2, N, 1);
    k_aggr<<<ablk, 256>>>(x1h, raw, x2, nullptr, csr, cnt, a2, cd2, gb, 1,
                          nullptr, nullptr, nullptr, N, 0);

    k_out<<<(N + 7) / 8, 128>>>(x2, t2w, t2b, out, N);
}

// round 9
// speedup vs baseline: 1.6661x; 1.6661x over previous
#include <cuda_runtime.h>
#include <cuda_bf16.h>
#include <cuda_fp16.h>
#include <math.h>

#define IN_DIM 256
#define H_DIM 64
#define OUT_DIM 16
#define MAXN 50000
#define MAXE 800000
#define CSR_CAP 128
#define FAGCN_EPS 0.3f

// ---------------- scratch (no allocation allowed) ----------------
__device__ float  g_raw[MAXN * H_DIM];
__device__ __half g_raw16[MAXN * H_DIM];
__device__ __half g_x1h[MAXN * H_DIM];
__device__ float  g_x2[MAXN * H_DIM];
__device__ int    g_cnt[MAXN];
__device__ int    g_csr[MAXN * CSR_CAP];
__device__ float  g_a1[MAXN];
__device__ float2 g_cd1[MAXN];
__device__ float  g_a2[MAXN];
__device__ float2 g_cd2[MAXN];

__device__ __forceinline__ float tanh_approx(float x) {
    float r;
    asm("tanh.approx.f32 %0, %1;" : "=f"(r) : "f"(x));
    return r;
}

// ---------------- CSR build ----------------
__global__ void k_zero(int* __restrict__ p, int n) {
    int i = blockIdx.x * blockDim.x + threadIdx.x;
    if (i < n) p[i] = 0;
}

__global__ void k_fill(const int* __restrict__ src, const int* __restrict__ dst,
                       int* __restrict__ cnt, int* __restrict__ csr,
                       int e0, int e1) {
    int i = e0 + blockIdx.x * blockDim.x + threadIdx.x;
    if (i < e1) {
        int t = dst[i];
        int pos = atomicAdd(&cnt[t], 1);
        if (pos < CSR_CAP) csr[t * CSR_CAP + pos] = src[i];
    }
}

// ---------------- t1: HMMA m16n8k16 (fp16 in, fp32 accum) ----------------
// Block = 256 thr (8 warps), computes 128 nodes x 64 outs.
// Warp w owns nodes [16w, 16w+16). W converted to fp16 smem once per block;
// h staged per 64-k tile as fp16. 128 MMAs per warp.
#define T1_BM 128
#define T1_WP 264   // W16 row pitch in halfs (256 + 8 pad)
#define T1_HP 72    // h16 row pitch in halfs (64 + 8 pad)
#define T1_SMEM ((64 * T1_WP + T1_BM * T1_HP) * 2)

__global__ void __launch_bounds__(256)
k_t1(const float* __restrict__ hin, const float* __restrict__ w,
     const float* __restrict__ b, float* __restrict__ out,
     __half* __restrict__ out16, int N) {
    extern __shared__ __half smh[];
    __half* w16 = smh;                    // [64][T1_WP]
    __half* h16 = smh + 64 * T1_WP;       // [128][T1_HP]
    int tx = threadIdx.x;
    int wp = tx >> 5;
    int lane = tx & 31;
    int g  = lane >> 2;    // group id (0..7)
    int tq = lane & 3;     // thread-in-group (0..3)

    // convert W[64][256] fp32 -> fp16 smem (once per block)
    const float4* w4 = (const float4*)w;   // 64 x 64 float4
#pragma unroll
    for (int i = 0; i < 16; i++) {
        int idx = tx + i * 256;     // 0..4095
        int j  = idx >> 6;          // out row 0..63
        int k4 = idx & 63;          // float4 col
        float4 v = w4[idx];
        __half2 p0 = __floats2half2_rn(v.x, v.y);
        __half2 p1 = __floats2half2_rn(v.z, v.w);
        uint2 u;
        u.x = *(unsigned*)&p0;
        u.y = *(unsigned*)&p1;
        *(uint2*)(w16 + j * T1_WP + k4 * 4) = u;
    }

    int n0 = blockIdx.x * T1_BM;
    float c[8][4];
#pragma unroll
    for (int nt = 0; nt < 8; nt++)
#pragma unroll
        for (int q = 0; q < 4; q++) c[nt][q] = 0.0f;

    for (int kt = 0; kt < 4; kt++) {
        __syncthreads();   // protect h16 reuse (and w16 stores on first iter)
        // stage h16: 128 nodes x 64 k, fp32 -> fp16
#pragma unroll
        for (int i = 0; i < 8; i++) {
            int idx = tx + i * 256;   // 0..2047
            int nl = idx >> 4;        // node local 0..127
            int k4 = idx & 15;        // float4 col 0..15
            int n  = n0 + nl;
            float4 v;
            if (n < N) v = *(const float4*)(hin + (size_t)n * IN_DIM + kt * 64 + k4 * 4);
            else       v = make_float4(0.f, 0.f, 0.f, 0.f);
            __half2 p0 = __floats2half2_rn(v.x, v.y);
            __half2 p1 = __floats2half2_rn(v.z, v.w);
            uint2 u;
            u.x = *(unsigned*)&p0;
            u.y = *(unsigned*)&p1;
            *(uint2*)(h16 + nl * T1_HP + k4 * 4) = u;
        }
        __syncthreads();

#pragma unroll
        for (int ks = 0; ks < 4; ks++) {
            // A fragments: rows (16wp+g, +8), k cols (kl..kl+1, kl+8..kl+9)
            int kl = ks * 16 + 2 * tq;
            const __half* arow = h16 + (wp * 16 + g) * T1_HP + kl;
            unsigned a0 = *(const unsigned*)(arow);               // (g,   k0)
            unsigned a1 = *(const unsigned*)(arow + 8 * T1_HP);   // (g+8, k0)
            unsigned a2 = *(const unsigned*)(arow + 8);           // (g,   k0+8)
            unsigned a3 = *(const unsigned*)(arow + 8 * T1_HP + 8); // (g+8, k0+8)
            int kg = kt * 64 + ks * 16 + 2 * tq;
#pragma unroll
            for (int nt = 0; nt < 8; nt++) {
                const __half* brow = w16 + (nt * 8 + g) * T1_WP + kg;
                unsigned b0 = *(const unsigned*)(brow);       // k lower, col g
                unsigned b1 = *(const unsigned*)(brow + 8);   // k upper, col g
                asm volatile(
                    "mma.sync.aligned.m16n8k16.row.col.f32.f16.f16.f32 "
                    "{%0,%1,%2,%3}, {%4,%5,%6,%7}, {%8,%9}, {%0,%1,%2,%3};"
                    : "+f"(c[nt][0]), "+f"(c[nt][1]), "+f"(c[nt][2]), "+f"(c[nt][3])
                    : "r"(a0), "r"(a1), "r"(a2), "r"(a3), "r"(b0), "r"(b1));
            }
        }
    }

    // epilogue: c[nt] = D rows {g, g+8}, cols {2tq, 2tq+1} of n-tile nt
    int node0 = n0 + wp * 16 + g;
    int node1 = node0 + 8;
#pragma unroll
    for (int nt = 0; nt < 8; nt++) {
        float2 bj = *(const float2*)(b + nt * 8 + 2 * tq);
        float2 r0, r1;
        r0.x = fmaxf(c[nt][0] + bj.x, 0.f);
        r0.y = fmaxf(c[nt][1] + bj.y, 0.f);
        r1.x = fmaxf(c[nt][2] + bj.x, 0.f);
        r1.y = fmaxf(c[nt][3] + bj.y, 0.f);
        int col = nt * 8 + 2 * tq;
        if (node0 < N) {
            *(float2*)(out + (size_t)node0 * H_DIM + col) = r0;
            __half2 hh = __floats2half2_rn(r0.x, r0.y);
            *(unsigned*)(out16 + (size_t)node0 * H_DIM + col) = *(unsigned*)&hh;
        }
        if (node1 < N) {
            *(float2*)(out + (size_t)node1 * H_DIM + col) = r1;
            __half2 hh = __floats2half2_rn(r1.x, r1.y);
            *(unsigned*)(out16 + (size_t)node1 * H_DIM + col) = *(unsigned*)&hh;
        }
    }
}

// ---------------- per-node gate precompute (+ degree norm) ----------------
__global__ void __launch_bounds__(256)
k_gate(const float* __restrict__ x, const float* __restrict__ gw,
       const int* __restrict__ cnt, float* __restrict__ a,
       float2* __restrict__ cd, int N) {
    int warp = (blockIdx.x * blockDim.x + threadIdx.x) >> 5;
    int lane = threadIdx.x & 31;
    if (warp >= N) return;
    float2 xv = *(const float2*)(x + (size_t)warp * 64 + lane * 2);
    float2 wa = *(const float2*)(gw + lane * 2);
    float2 wc = *(const float2*)(gw + 64 + lane * 2);
    float pa = xv.x * wa.x + xv.y * wa.y;
    float pc = xv.x * wc.x + xv.y * wc.y;
#pragma unroll
    for (int o = 16; o; o >>= 1) {
        pa += __shfl_xor_sync(0xffffffffu, pa, o);
        pc += __shfl_xor_sync(0xffffffffu, pc, o);
    }
    if (lane == 0) {
        a[warp] = pa;
        float d = rsqrtf(fmaxf((float)cnt[warp], 1.0f));
        cd[warp] = make_float2(pc, d);
    }
}

// ---------------- aggregation: HFMA2 batches, 2 nodes/warp ----------------
__global__ void __launch_bounds__(256)
k_aggr(const __half* __restrict__ x, const float* __restrict__ raw,
       float* __restrict__ xn_f, __half* __restrict__ xn_h,
       const int* __restrict__ csr, const int* __restrict__ cnt,
       const float* __restrict__ a, const float2* __restrict__ cd,
       const float* __restrict__ gbp, int layer,
       const float* __restrict__ gw_next, float* __restrict__ a_next,
       float2* __restrict__ cd_next,
       int N, int fuse) {
    int warp = (blockIdx.x * blockDim.x + threadIdx.x) >> 5;
    int lane = threadIdx.x & 31;
    int half = lane >> 4;
    int l = lane & 15;

    int t = warp * 2 + half;
    bool nvalid = (t < N);
    int tc = nvalid ? t : 0;

    int deg = nvalid ? min(cnt[tc], CSR_CAP) : 0;
    int start = tc * CSR_CAP;
    float2 cdt = cd[tc];
    float base = a[tc] + gbp[layer];
    float dt = cdt.y;

    int deg_o = __shfl_xor_sync(0xffffffffu, deg, 16);
    int degmax = max(deg, deg_o);

    float4 rv = nvalid ? *(const float4*)(raw + (size_t)t * 64 + l * 4)
                       : make_float4(0.f, 0.f, 0.f, 0.f);
    float4 acc;
    acc.x = FAGCN_EPS * rv.x;
    acc.y = FAGCN_EPS * rv.y;
    acc.z = FAGCN_EPS * rv.z;
    acc.w = FAGCN_EPS * rv.w;

    for (int b0 = 0; b0 < degmax; b0 += 16) {
        int ei = b0 + l;
        int sb = 0;
        unsigned ep = 0;
        if (ei < deg) {
            sb = csr[start + ei];
            float2 cs = cd[sb];
            float ev = tanh_approx(base + cs.x) * dt * cs.y;
            __half2 e2 = __float2half2_rn(ev);
            ep = *(unsigned*)&e2;
        }
        int mmax = min(16, degmax - b0);
        __half2 hacc0 = __float2half2_rn(0.0f);
        __half2 hacc1 = hacc0;
        if (mmax == 16) {
#pragma unroll
            for (int bq = 0; bq < 16; bq++) {
                int srcl = (lane & 16) | bq;
                unsigned e = __shfl_sync(0xffffffffu, ep, srcl);
                int s  = __shfl_sync(0xffffffffu, sb, srcl);
                uint2 u = *(const uint2*)(x + (size_t)s * 64 + l * 4);
                hacc0 = __hfma2(*(__half2*)&u.x, *(__half2*)&e, hacc0);
                hacc1 = __hfma2(*(__half2*)&u.y, *(__half2*)&e, hacc1);
            }
        } else {
            for (int bq = 0; bq < mmax; bq++) {
                int srcl = (lane & 16) | bq;
                unsigned e = __shfl_sync(0xffffffffu, ep, srcl);
                int s  = __shfl_sync(0xffffffffu, sb, srcl);
                uint2 u = *(const uint2*)(x + (size_t)s * 64 + l * 4);
                hacc0 = __hfma2(*(__half2*)&u.x, *(__half2*)&e, hacc0);
                hacc1 = __hfma2(*(__half2*)&u.y, *(__half2*)&e, hacc1);
            }
        }
        float2 f0 = __half22float2(hacc0);
        float2 f1 = __half22float2(hacc1);
        acc.x += f0.x;
        acc.y += f0.y;
        acc.z += f1.x;
        acc.w += f1.y;
    }

    if (nvalid) {
        if (xn_f)
            *(float4*)(xn_f + (size_t)t * 64 + l * 4) = acc;
        if (xn_h) {
            __half2 h0 = __floats2half2_rn(acc.x, acc.y);
            __half2 h1 = __floats2half2_rn(acc.z, acc.w);
            uint2 u;
            u.x = *(unsigned*)&h0;
            u.y = *(unsigned*)&h1;
            *(uint2*)(xn_h + (size_t)t * 64 + l * 4) = u;
        }
    }

    if (fuse && nvalid) {
        float4 wa = *(const float4*)(gw_next + l * 4);
        float4 wc = *(const float4*)(gw_next + 64 + l * 4);
        float pa = acc.x * wa.x + acc.y * wa.y + acc.z * wa.z + acc.w * wa.w;
        float pc = acc.x * wc.x + acc.y * wc.y + acc.z * wc.z + acc.w * wc.w;
#pragma unroll
        for (int o = 8; o; o >>= 1) {
            pa += __shfl_xor_sync(0xffffffffu, pa, o);
            pc += __shfl_xor_sync(0xffffffffu, pc, o);
        }
        if (l == 0) {
            a_next[t] = pa;
            cd_next[t] = make_float2(pc, dt);
        }
    }
}

// ---------------- output ----------------
__global__ void k_out(const float* __restrict__ x, const float* __restrict__ w2,
                      const float* __restrict__ b2, float* __restrict__ out, int N) {
    __shared__ float wS[16 * 64];
    __shared__ float xS[8][64];
    int t = threadIdx.x;
    for (int idx = t; idx < 16 * 64; idx += 128) wS[idx] = w2[idx];

    int node = blockIdx.x * 8 + (t >> 4);
    int j = t & 15;
    bool valid = (node < N);
    int nc = valid ? node : (N - 1);

    __syncthreads();
    {
        const float4* xp = (const float4*)(x + (size_t)nc * 64);
        ((float4*)xS[t >> 4])[j] = xp[j];
    }
    __syncthreads();

    const float4* xr = (const float4*)xS[t >> 4];
    const float4* wr = (const float4*)(wS + j * 64);
    float acc = b2[j];
#pragma unroll
    for (int k = 0; k < 16; k++) {
        float4 av = xr[k];
        float4 wv = wr[k];
        acc += av.x * wv.x + av.y * wv.y + av.z * wv.z + av.w * wv.w;
    }
    float m = acc;
    for (int o = 8; o; o >>= 1) m = fmaxf(m, __shfl_xor_sync(0xffffffffu, m, o));
    float ex = expf(acc - m);
    float s = ex;
    for (int o = 8; o; o >>= 1) s += __shfl_xor_sync(0xffffffffu, s, o);
    if (valid) out[(size_t)node * 16 + j] = acc - m - logf(s);
}

// ---------------- launch ----------------
extern "C" void kernel_launch(void* const* d_in, const int* in_sizes, int n_in,
                              void* d_out, int out_size) {
    const float* h   = (const float*)d_in[0];
    const int*   src = (const int*)  d_in[1];
    const int*   dst = (const int*)  d_in[2];
    const float* t1w = (const float*)d_in[3];
    const float* t1b = (const float*)d_in[4];
    const float* gw  = (const float*)d_in[5];
    const float* gb  = (const float*)d_in[6];
    const float* t2w = (const float*)d_in[7];
    const float* t2b = (const float*)d_in[8];
    float* out = (float*)d_out;

    int N = in_sizes[0] / IN_DIM;
    int E = in_sizes[1];

    float *raw, *x2, *a1, *a2;
    __half *raw16, *x1h;
    float2 *cd1, *cd2;
    int *cnt, *csr;
    cudaGetSymbolAddress((void**)&raw,   g_raw);
    cudaGetSymbolAddress((void**)&raw16, g_raw16);
    cudaGetSymbolAddress((void**)&x1h,   g_x1h);
    cudaGetSymbolAddress((void**)&x2,    g_x2);
    cudaGetSymbolAddress((void**)&cnt,   g_cnt);
    cudaGetSymbolAddress((void**)&csr,   g_csr);
    cudaGetSymbolAddress((void**)&a1,    g_a1);
    cudaGetSymbolAddress((void**)&a2,    g_a2);
    cudaGetSymbolAddress((void**)&cd1,   g_cd1);
    cudaGetSymbolAddress((void**)&cd2,   g_cd2);

    // kernel order: zero(1), fill_a(2), fill_b(3), t1(4 <- ncu capture slot),
    // gate(5), aggr0(6), aggr1(7), out(8)
    k_zero<<<(N + 255) / 256, 256>>>(cnt, N);
    int Eh = E / 2;
    k_fill<<<(Eh + 255) / 256, 256>>>(src, dst, cnt, csr, 0, Eh);
    k_fill<<<(E - Eh + 255) / 256, 256>>>(src, dst, cnt, csr, Eh, E);

    cudaFuncSetAttribute(k_t1, cudaFuncAttributeMaxDynamicSharedMemorySize, T1_SMEM);
    k_t1<<<(N + T1_BM - 1) / T1_BM, 256, T1_SMEM>>>(h, t1w, t1b, raw, raw16, N);

    int gblk = (N * 32 + 255) / 256;
    k_gate<<<gblk, 256>>>(raw, gw, cnt, a1, cd1, N);

    int ablk = (N + 15) / 16;
    k_aggr<<<ablk, 256>>>(raw16, raw, nullptr, x1h, csr, cnt, a1, cd1, gb, 0,
                          gw + 128, a2, cd2, N, 1);
    k_aggr<<<ablk, 256>>>(x1h, raw, x2, nullptr, csr, cnt, a2, cd2, gb, 1,
                          nullptr, nullptr, nullptr, N, 0);

    k_out<<<(N + 7) / 8, 128>>>(x2, t2w, t2b, out, N);
}

// round 10
// speedup vs baseline: 1.6893x; 1.0140x over previous
#include <cuda_runtime.h>
#include <cuda_bf16.h>
#include <cuda_fp16.h>
#include <math.h>

#define IN_DIM 256
#define H_DIM 64
#define OUT_DIM 16
#define MAXN 50000
#define MAXE 800000
#define CSR_CAP 128
#define FAGCN_EPS 0.3f

// ---------------- scratch (no allocation allowed) ----------------
__device__ float  g_raw[MAXN * H_DIM];
__device__ __half g_raw16[MAXN * H_DIM];
__device__ __half g_x1h[MAXN * H_DIM];
__device__ int    g_cnt[MAXN];
__device__ int    g_csr[MAXN * CSR_CAP];
__device__ float  g_a1[MAXN];
__device__ float2 g_cd1[MAXN];
__device__ float  g_a2[MAXN];
__device__ float2 g_cd2[MAXN];

__device__ __forceinline__ float tanh_approx(float x) {
    float r;
    asm("tanh.approx.f32 %0, %1;" : "=f"(r) : "f"(x));
    return r;
}

// ---------------- CSR build ----------------
__global__ void k_zero(int* __restrict__ p, int n) {
    int i = blockIdx.x * blockDim.x + threadIdx.x;
    if (i < n) p[i] = 0;
}

__global__ void k_fill(const int* __restrict__ src, const int* __restrict__ dst,
                       int* __restrict__ cnt, int* __restrict__ csr, int E) {
    int i = blockIdx.x * blockDim.x + threadIdx.x;
    if (i < E) {
        int t = dst[i];
        int pos = atomicAdd(&cnt[t], 1);
        if (pos < CSR_CAP) csr[t * CSR_CAP + pos] = src[i];
    }
}

// ---------------- t1: HMMA m16n8k16 + fused gate precompute ----------------
// Block = 256 thr (8 warps), 128 nodes x 64 outs. After the MMA epilogue each
// thread holds rows {base+g, base+g+8} cols {8nt+2tq, +1}; gate partials are
// quad-reduced (lanes g*4+tq share a row pair).
#define T1_BM 128
#define T1_WP 264
#define T1_HP 72
#define T1_SMEM ((64 * T1_WP + T1_BM * T1_HP) * 2)

__global__ void __launch_bounds__(256)
k_t1(const float* __restrict__ hin, const float* __restrict__ w,
     const float* __restrict__ b, float* __restrict__ out,
     __half* __restrict__ out16,
     const float* __restrict__ gw,      // layer-0 gate weights [128]
     const int* __restrict__ cnt,
     float* __restrict__ a1, float2* __restrict__ cd1, int N) {
    extern __shared__ __half smh[];
    __half* w16 = smh;                    // [64][T1_WP]
    __half* h16 = smh + 64 * T1_WP;       // [128][T1_HP]
    int tx = threadIdx.x;
    int wp = tx >> 5;
    int lane = tx & 31;
    int g  = lane >> 2;
    int tq = lane & 3;

    const float4* w4 = (const float4*)w;
#pragma unroll
    for (int i = 0; i < 16; i++) {
        int idx = tx + i * 256;
        int j  = idx >> 6;
        int k4 = idx & 63;
        float4 v = w4[idx];
        __half2 p0 = __floats2half2_rn(v.x, v.y);
        __half2 p1 = __floats2half2_rn(v.z, v.w);
        uint2 u;
        u.x = *(unsigned*)&p0;
        u.y = *(unsigned*)&p1;
        *(uint2*)(w16 + j * T1_WP + k4 * 4) = u;
    }

    int n0 = blockIdx.x * T1_BM;
    float c[8][4];
#pragma unroll
    for (int nt = 0; nt < 8; nt++)
#pragma unroll
        for (int q = 0; q < 4; q++) c[nt][q] = 0.0f;

    for (int kt = 0; kt < 4; kt++) {
        __syncthreads();
#pragma unroll
        for (int i = 0; i < 8; i++) {
            int idx = tx + i * 256;
            int nl = idx >> 4;
            int k4 = idx & 15;
            int n  = n0 + nl;
            float4 v;
            if (n < N) v = *(const float4*)(hin + (size_t)n * IN_DIM + kt * 64 + k4 * 4);
            else       v = make_float4(0.f, 0.f, 0.f, 0.f);
            __half2 p0 = __floats2half2_rn(v.x, v.y);
            __half2 p1 = __floats2half2_rn(v.z, v.w);
            uint2 u;
            u.x = *(unsigned*)&p0;
            u.y = *(unsigned*)&p1;
            *(uint2*)(h16 + nl * T1_HP + k4 * 4) = u;
        }
        __syncthreads();

#pragma unroll
        for (int ks = 0; ks < 4; ks++) {
            int kl = ks * 16 + 2 * tq;
            const __half* arow = h16 + (wp * 16 + g) * T1_HP + kl;
            unsigned a0 = *(const unsigned*)(arow);
            unsigned a1f = *(const unsigned*)(arow + 8 * T1_HP);
            unsigned a2f = *(const unsigned*)(arow + 8);
            unsigned a3 = *(const unsigned*)(arow + 8 * T1_HP + 8);
            int kg = kt * 64 + ks * 16 + 2 * tq;
#pragma unroll
            for (int nt = 0; nt < 8; nt++) {
                const __half* brow = w16 + (nt * 8 + g) * T1_WP + kg;
                unsigned b0 = *(const unsigned*)(brow);
                unsigned b1 = *(const unsigned*)(brow + 8);
                asm volatile(
                    "mma.sync.aligned.m16n8k16.row.col.f32.f16.f16.f32 "
                    "{%0,%1,%2,%3}, {%4,%5,%6,%7}, {%8,%9}, {%0,%1,%2,%3};"
                    : "+f"(c[nt][0]), "+f"(c[nt][1]), "+f"(c[nt][2]), "+f"(c[nt][3])
                    : "r"(a0), "r"(a1f), "r"(a2f), "r"(a3), "r"(b0), "r"(b1));
            }
        }
    }

    // epilogue: bias+relu, store fp32/fp16, accumulate gate partials
    int node0 = n0 + wp * 16 + g;
    int node1 = node0 + 8;
    float pa0 = 0.f, pc0 = 0.f, pa1 = 0.f, pc1 = 0.f;
#pragma unroll
    for (int nt = 0; nt < 8; nt++) {
        int col = nt * 8 + 2 * tq;
        float2 bj = *(const float2*)(b + col);
        float2 r0, r1;
        r0.x = fmaxf(c[nt][0] + bj.x, 0.f);
        r0.y = fmaxf(c[nt][1] + bj.y, 0.f);
        r1.x = fmaxf(c[nt][2] + bj.x, 0.f);
        r1.y = fmaxf(c[nt][3] + bj.y, 0.f);
        if (node0 < N) {
            *(float2*)(out + (size_t)node0 * H_DIM + col) = r0;
            __half2 hh = __floats2half2_rn(r0.x, r0.y);
            *(unsigned*)(out16 + (size_t)node0 * H_DIM + col) = *(unsigned*)&hh;
        }
        if (node1 < N) {
            *(float2*)(out + (size_t)node1 * H_DIM + col) = r1;
            __half2 hh = __floats2half2_rn(r1.x, r1.y);
            *(unsigned*)(out16 + (size_t)node1 * H_DIM + col) = *(unsigned*)&hh;
        }
        float2 gwa = *(const float2*)(gw + col);
        float2 gwc = *(const float2*)(gw + 64 + col);
        pa0 += gwa.x * r0.x + gwa.y * r0.y;
        pc0 += gwc.x * r0.x + gwc.y * r0.y;
        pa1 += gwa.x * r1.x + gwa.y * r1.y;
        pc1 += gwc.x * r1.x + gwc.y * r1.y;
    }
    // quad reduction (lanes g*4 + tq)
#pragma unroll
    for (int o = 1; o <= 2; o <<= 1) {
        pa0 += __shfl_xor_sync(0xffffffffu, pa0, o);
        pc0 += __shfl_xor_sync(0xffffffffu, pc0, o);
        pa1 += __shfl_xor_sync(0xffffffffu, pa1, o);
        pc1 += __shfl_xor_sync(0xffffffffu, pc1, o);
    }
    if (tq == 0) {
        if (node0 < N) {
            a1[node0] = pa0;
            float d = rsqrtf(fmaxf((float)cnt[node0], 1.0f));
            cd1[node0] = make_float2(pc0, d);
        }
        if (node1 < N) {
            a1[node1] = pa1;
            float d = rsqrtf(fmaxf((float)cnt[node1], 1.0f));
            cd1[node1] = make_float2(pc1, d);
        }
    }
}

// ---------------- aggregation layer 0: HFMA2, 2 nodes/warp, fused next-gate ----------------
__global__ void __launch_bounds__(256)
k_aggr(const __half* __restrict__ x, const float* __restrict__ raw,
       __half* __restrict__ xn_h,
       const int* __restrict__ csr, const int* __restrict__ cnt,
       const float* __restrict__ a, const float2* __restrict__ cd,
       const float* __restrict__ gbp, int layer,
       const float* __restrict__ gw_next, float* __restrict__ a_next,
       float2* __restrict__ cd_next, int N) {
    int warp = (blockIdx.x * blockDim.x + threadIdx.x) >> 5;
    int lane = threadIdx.x & 31;
    int half = lane >> 4;
    int l = lane & 15;

    int t = warp * 2 + half;
    bool nvalid = (t < N);
    int tc = nvalid ? t : 0;

    int deg = nvalid ? min(cnt[tc], CSR_CAP) : 0;
    int start = tc * CSR_CAP;
    float2 cdt = cd[tc];
    float base = a[tc] + gbp[layer];
    float dt = cdt.y;

    int deg_o = __shfl_xor_sync(0xffffffffu, deg, 16);
    int degmax = max(deg, deg_o);

    float4 rv = nvalid ? *(const float4*)(raw + (size_t)t * 64 + l * 4)
                       : make_float4(0.f, 0.f, 0.f, 0.f);
    float4 acc;
    acc.x = FAGCN_EPS * rv.x;
    acc.y = FAGCN_EPS * rv.y;
    acc.z = FAGCN_EPS * rv.z;
    acc.w = FAGCN_EPS * rv.w;

    for (int b0 = 0; b0 < degmax; b0 += 16) {
        int ei = b0 + l;
        int sb = 0;
        unsigned ep = 0;
        if (ei < deg) {
            sb = csr[start + ei];
            float2 cs = cd[sb];
            float ev = tanh_approx(base + cs.x) * dt * cs.y;
            __half2 e2 = __float2half2_rn(ev);
            ep = *(unsigned*)&e2;
        }
        int mmax = min(16, degmax - b0);
        __half2 hacc0 = __float2half2_rn(0.0f);
        __half2 hacc1 = hacc0;
        if (mmax == 16) {
#pragma unroll
            for (int bq = 0; bq < 16; bq++) {
                int srcl = (lane & 16) | bq;
                unsigned e = __shfl_sync(0xffffffffu, ep, srcl);
                int s  = __shfl_sync(0xffffffffu, sb, srcl);
                uint2 u = *(const uint2*)(x + (size_t)s * 64 + l * 4);
                hacc0 = __hfma2(*(__half2*)&u.x, *(__half2*)&e, hacc0);
                hacc1 = __hfma2(*(__half2*)&u.y, *(__half2*)&e, hacc1);
            }
        } else {
            for (int bq = 0; bq < mmax; bq++) {
                int srcl = (lane & 16) | bq;
                unsigned e = __shfl_sync(0xffffffffu, ep, srcl);
                int s  = __shfl_sync(0xffffffffu, sb, srcl);
                uint2 u = *(const uint2*)(x + (size_t)s * 64 + l * 4);
                hacc0 = __hfma2(*(__half2*)&u.x, *(__half2*)&e, hacc0);
                hacc1 = __hfma2(*(__half2*)&u.y, *(__half2*)&e, hacc1);
            }
        }
        float2 f0 = __half22float2(hacc0);
        float2 f1 = __half22float2(hacc1);
        acc.x += f0.x;
        acc.y += f0.y;
        acc.z += f1.x;
        acc.w += f1.y;
    }

    if (nvalid) {
        __half2 h0 = __floats2half2_rn(acc.x, acc.y);
        __half2 h1 = __floats2half2_rn(acc.z, acc.w);
        uint2 u;
        u.x = *(unsigned*)&h0;
        u.y = *(unsigned*)&h1;
        *(uint2*)(xn_h + (size_t)t * 64 + l * 4) = u;

        float4 wa = *(const float4*)(gw_next + l * 4);
        float4 wc = *(const float4*)(gw_next + 64 + l * 4);
        float pa = acc.x * wa.x + acc.y * wa.y + acc.z * wa.z + acc.w * wa.w;
        float pc = acc.x * wc.x + acc.y * wc.y + acc.z * wc.z + acc.w * wc.w;
#pragma unroll
        for (int o = 8; o; o >>= 1) {
            pa += __shfl_xor_sync(0xffffffffu, pa, o);
            pc += __shfl_xor_sync(0xffffffffu, pc, o);
        }
        if (l == 0) {
            a_next[t] = pa;
            cd_next[t] = make_float2(pc, dt);
        }
    }
}

// ---------------- aggregation layer 1 + t2 + log_softmax (fused output) ----------------
__global__ void __launch_bounds__(256)
k_aggr_out(const __half* __restrict__ x, const float* __restrict__ raw,
           const int* __restrict__ csr, const int* __restrict__ cnt,
           const float* __restrict__ a, const float2* __restrict__ cd,
           const float* __restrict__ gbp, int layer,
           const float* __restrict__ w2, const float* __restrict__ b2,
           float* __restrict__ out, int N) {
    __shared__ float wS[16 * 64];
    __shared__ float xS[16][68];
    int tx = threadIdx.x;
    // stage w2 (16x64)
#pragma unroll
    for (int i = 0; i < 4; i++) wS[tx + i * 256] = w2[tx + i * 256];

    int warp = (blockIdx.x * blockDim.x + tx) >> 5;
    int lane = tx & 31;
    int half = lane >> 4;
    int l = lane & 15;
    int nodeLocal = (tx >> 5) * 2 + half;   // 0..15

    int t = warp * 2 + half;
    bool nvalid = (t < N);
    int tc = nvalid ? t : 0;

    int deg = nvalid ? min(cnt[tc], CSR_CAP) : 0;
    int start = tc * CSR_CAP;
    float2 cdt = cd[tc];
    float base = a[tc] + gbp[layer];
    float dt = cdt.y;

    int deg_o = __shfl_xor_sync(0xffffffffu, deg, 16);
    int degmax = max(deg, deg_o);

    float4 rv = nvalid ? *(const float4*)(raw + (size_t)t * 64 + l * 4)
                       : make_float4(0.f, 0.f, 0.f, 0.f);
    float4 acc;
    acc.x = FAGCN_EPS * rv.x;
    acc.y = FAGCN_EPS * rv.y;
    acc.z = FAGCN_EPS * rv.z;
    acc.w = FAGCN_EPS * rv.w;

    for (int b0 = 0; b0 < degmax; b0 += 16) {
        int ei = b0 + l;
        int sb = 0;
        unsigned ep = 0;
        if (ei < deg) {
            sb = csr[start + ei];
            float2 cs = cd[sb];
            float ev = tanh_approx(base + cs.x) * dt * cs.y;
            __half2 e2 = __float2half2_rn(ev);
            ep = *(unsigned*)&e2;
        }
        int mmax = min(16, degmax - b0);
        __half2 hacc0 = __float2half2_rn(0.0f);
        __half2 hacc1 = hacc0;
        if (mmax == 16) {
#pragma unroll
            for (int bq = 0; bq < 16; bq++) {
                int srcl = (lane & 16) | bq;
                unsigned e = __shfl_sync(0xffffffffu, ep, srcl);
                int s  = __shfl_sync(0xffffffffu, sb, srcl);
                uint2 u = *(const uint2*)(x + (size_t)s * 64 + l * 4);
                hacc0 = __hfma2(*(__half2*)&u.x, *(__half2*)&e, hacc0);
                hacc1 = __hfma2(*(__half2*)&u.y, *(__half2*)&e, hacc1);
            }
        } else {
            for (int bq = 0; bq < mmax; bq++) {
                int srcl = (lane & 16) | bq;
                unsigned e = __shfl_sync(0xffffffffu, ep, srcl);
                int s  = __shfl_sync(0xffffffffu, sb, srcl);
                uint2 u = *(const uint2*)(x + (size_t)s * 64 + l * 4);
                hacc0 = __hfma2(*(__half2*)&u.x, *(__half2*)&e, hacc0);
                hacc1 = __hfma2(*(__half2*)&u.y, *(__half2*)&e, hacc1);
            }
        }
        float2 f0 = __half22float2(hacc0);
        float2 f1 = __half22float2(hacc1);
        acc.x += f0.x;
        acc.y += f0.y;
        acc.z += f1.x;
        acc.w += f1.y;
    }

    *(float4*)(&xS[nodeLocal][l * 4]) = acc;
    __syncthreads();

    // t2 GEMV + log_softmax: 16 nodes x 16 outs
    int nl2 = tx >> 4;
    int j = tx & 15;
    int node = blockIdx.x * 16 + nl2;
    const float4* xr = (const float4*)(&xS[nl2][0]);
    const float4* wr = (const float4*)(wS + j * 64);
    float logit = b2[j];
#pragma unroll
    for (int k = 0; k < 16; k++) {
        float4 av = xr[k];
        float4 wv = wr[k];
        logit += av.x * wv.x + av.y * wv.y + av.z * wv.z + av.w * wv.w;
    }
    float m = logit;
#pragma unroll
    for (int o = 8; o; o >>= 1) m = fmaxf(m, __shfl_xor_sync(0xffffffffu, m, o));
    float ex = expf(logit - m);
    float s = ex;
#pragma unroll
    for (int o = 8; o; o >>= 1) s += __shfl_xor_sync(0xffffffffu, s, o);
    if (node < N) out[(size_t)node * 16 + j] = logit - m - logf(s);
}

// ---------------- launch ----------------
extern "C" void kernel_launch(void* const* d_in, const int* in_sizes, int n_in,
                              void* d_out, int out_size) {
    const float* h   = (const float*)d_in[0];
    const int*   src = (const int*)  d_in[1];
    const int*   dst = (const int*)  d_in[2];
    const float* t1w = (const float*)d_in[3];
    const float* t1b = (const float*)d_in[4];
    const float* gw  = (const float*)d_in[5];
    const float* gb  = (const float*)d_in[6];
    const float* t2w = (const float*)d_in[7];
    const float* t2b = (const float*)d_in[8];
    float* out = (float*)d_out;

    int N = in_sizes[0] / IN_DIM;
    int E = in_sizes[1];

    float *raw, *a1, *a2;
    __half *raw16, *x1h;
    float2 *cd1, *cd2;
    int *cnt, *csr;
    cudaGetSymbolAddress((void**)&raw,   g_raw);
    cudaGetSymbolAddress((void**)&raw16, g_raw16);
    cudaGetSymbolAddress((void**)&x1h,   g_x1h);
    cudaGetSymbolAddress((void**)&cnt,   g_cnt);
    cudaGetSymbolAddress((void**)&csr,   g_csr);
    cudaGetSymbolAddress((void**)&a1,    g_a1);
    cudaGetSymbolAddress((void**)&a2,    g_a2);
    cudaGetSymbolAddress((void**)&cd1,   g_cd1);
    cudaGetSymbolAddress((void**)&cd2,   g_cd2);

    // launch order: zero(1), fill(2), t1+gate(3), aggr0(4 <- ncu slot), aggr_out(5)
    k_zero<<<(N + 255) / 256, 256>>>(cnt, N);
    k_fill<<<(E + 255) / 256, 256>>>(src, dst, cnt, csr, E);

    cudaFuncSetAttribute(k_t1, cudaFuncAttributeMaxDynamicSharedMemorySize, T1_SMEM);
    k_t1<<<(N + T1_BM - 1) / T1_BM, 256, T1_SMEM>>>(h, t1w, t1b, raw, raw16,
                                                    gw, cnt, a1, cd1, N);

    int ablk = (N + 15) / 16;
    k_aggr<<<ablk, 256>>>(raw16, raw, x1h, csr, cnt, a1, cd1, gb, 0,
                          gw + 128, a2, cd2, N);
    k_aggr_out<<<ablk, 256>>>(x1h, raw, csr, cnt, a2, cd2, gb, 1,
                              t2w, t2b, out, N);
}

// round 11
// speedup vs baseline: 1.7927x; 1.0612x over previous
#include <cuda_runtime.h>
#include <cuda_bf16.h>
#include <cuda_fp16.h>
#include <math.h>

#define IN_DIM 256
#define H_DIM 64
#define OUT_DIM 16
#define MAXN 50000
#define MAXE 800000
#define CSR_CAP 128
#define FAGCN_EPS 0.3f

// ---------------- scratch (no allocation allowed) ----------------
__device__ float  g_raw[MAXN * H_DIM];
__device__ __half g_raw16[MAXN * H_DIM];
__device__ __half g_x1h[MAXN * H_DIM];
__device__ int    g_cnt[MAXN];
__device__ int    g_csr[MAXN * CSR_CAP];
__device__ __half g_ecoef[MAXN * CSR_CAP];
__device__ float  g_a1[MAXN];
__device__ float2 g_cd1[MAXN];
__device__ float  g_a2[MAXN];
__device__ float2 g_cd2[MAXN];

__device__ __forceinline__ float tanh_approx(float x) {
    float r;
    asm("tanh.approx.f32 %0, %1;" : "=f"(r) : "f"(x));
    return r;
}

// ---------------- CSR build ----------------
__global__ void k_zero(int* __restrict__ p, int n) {
    int i = blockIdx.x * blockDim.x + threadIdx.x;
    if (i < n) p[i] = 0;
}

__global__ void k_fill(const int* __restrict__ src, const int* __restrict__ dst,
                       int* __restrict__ cnt, int* __restrict__ csr, int E) {
    int i = blockIdx.x * blockDim.x + threadIdx.x;
    if (i < E) {
        int t = dst[i];
        int pos = atomicAdd(&cnt[t], 1);
        if (pos < CSR_CAP) csr[t * CSR_CAP + pos] = src[i];
    }
}

// ---------------- t1: HMMA m16n8k16 + fused gate precompute ----------------
#define T1_BM 128
#define T1_WP 264
#define T1_HP 72
#define T1_SMEM ((64 * T1_WP + T1_BM * T1_HP) * 2)

__global__ void __launch_bounds__(256)
k_t1(const float* __restrict__ hin, const float* __restrict__ w,
     const float* __restrict__ b, float* __restrict__ out,
     __half* __restrict__ out16,
     const float* __restrict__ gw,
     const int* __restrict__ cnt,
     float* __restrict__ a1, float2* __restrict__ cd1, int N) {
    extern __shared__ __half smh[];
    __half* w16 = smh;
    __half* h16 = smh + 64 * T1_WP;
    int tx = threadIdx.x;
    int wp = tx >> 5;
    int lane = tx & 31;
    int g  = lane >> 2;
    int tq = lane & 3;

    const float4* w4 = (const float4*)w;
#pragma unroll
    for (int i = 0; i < 16; i++) {
        int idx = tx + i * 256;
        int j  = idx >> 6;
        int k4 = idx & 63;
        float4 v = w4[idx];
        __half2 p0 = __floats2half2_rn(v.x, v.y);
        __half2 p1 = __floats2half2_rn(v.z, v.w);
        uint2 u;
        u.x = *(unsigned*)&p0;
        u.y = *(unsigned*)&p1;
        *(uint2*)(w16 + j * T1_WP + k4 * 4) = u;
    }

    int n0 = blockIdx.x * T1_BM;
    float c[8][4];
#pragma unroll
    for (int nt = 0; nt < 8; nt++)
#pragma unroll
        for (int q = 0; q < 4; q++) c[nt][q] = 0.0f;

    for (int kt = 0; kt < 4; kt++) {
        __syncthreads();
#pragma unroll
        for (int i = 0; i < 8; i++) {
            int idx = tx + i * 256;
            int nl = idx >> 4;
            int k4 = idx & 15;
            int n  = n0 + nl;
            float4 v;
            if (n < N) v = *(const float4*)(hin + (size_t)n * IN_DIM + kt * 64 + k4 * 4);
            else       v = make_float4(0.f, 0.f, 0.f, 0.f);
            __half2 p0 = __floats2half2_rn(v.x, v.y);
            __half2 p1 = __floats2half2_rn(v.z, v.w);
            uint2 u;
            u.x = *(unsigned*)&p0;
            u.y = *(unsigned*)&p1;
            *(uint2*)(h16 + nl * T1_HP + k4 * 4) = u;
        }
        __syncthreads();

#pragma unroll
        for (int ks = 0; ks < 4; ks++) {
            int kl = ks * 16 + 2 * tq;
            const __half* arow = h16 + (wp * 16 + g) * T1_HP + kl;
            unsigned a0 = *(const unsigned*)(arow);
            unsigned a1f = *(const unsigned*)(arow + 8 * T1_HP);
            unsigned a2f = *(const unsigned*)(arow + 8);
            unsigned a3 = *(const unsigned*)(arow + 8 * T1_HP + 8);
            int kg = kt * 64 + ks * 16 + 2 * tq;
#pragma unroll
            for (int nt = 0; nt < 8; nt++) {
                const __half* brow = w16 + (nt * 8 + g) * T1_WP + kg;
                unsigned b0 = *(const unsigned*)(brow);
                unsigned b1 = *(const unsigned*)(brow + 8);
                asm volatile(
                    "mma.sync.aligned.m16n8k16.row.col.f32.f16.f16.f32 "
                    "{%0,%1,%2,%3}, {%4,%5,%6,%7}, {%8,%9}, {%0,%1,%2,%3};"
                    : "+f"(c[nt][0]), "+f"(c[nt][1]), "+f"(c[nt][2]), "+f"(c[nt][3])
                    : "r"(a0), "r"(a1f), "r"(a2f), "r"(a3), "r"(b0), "r"(b1));
            }
        }
    }

    int node0 = n0 + wp * 16 + g;
    int node1 = node0 + 8;
    float pa0 = 0.f, pc0 = 0.f, pa1 = 0.f, pc1 = 0.f;
#pragma unroll
    for (int nt = 0; nt < 8; nt++) {
        int col = nt * 8 + 2 * tq;
        float2 bj = *(const float2*)(b + col);
        float2 r0, r1;
        r0.x = fmaxf(c[nt][0] + bj.x, 0.f);
        r0.y = fmaxf(c[nt][1] + bj.y, 0.f);
        r1.x = fmaxf(c[nt][2] + bj.x, 0.f);
        r1.y = fmaxf(c[nt][3] + bj.y, 0.f);
        if (node0 < N) {
            *(float2*)(out + (size_t)node0 * H_DIM + col) = r0;
            __half2 hh = __floats2half2_rn(r0.x, r0.y);
            *(unsigned*)(out16 + (size_t)node0 * H_DIM + col) = *(unsigned*)&hh;
        }
        if (node1 < N) {
            *(float2*)(out + (size_t)node1 * H_DIM + col) = r1;
            __half2 hh = __floats2half2_rn(r1.x, r1.y);
            *(unsigned*)(out16 + (size_t)node1 * H_DIM + col) = *(unsigned*)&hh;
        }
        float2 gwa = *(const float2*)(gw + col);
        float2 gwc = *(const float2*)(gw + 64 + col);
        pa0 += gwa.x * r0.x + gwa.y * r0.y;
        pc0 += gwc.x * r0.x + gwc.y * r0.y;
        pa1 += gwa.x * r1.x + gwa.y * r1.y;
        pc1 += gwc.x * r1.x + gwc.y * r1.y;
    }
#pragma unroll
    for (int o = 1; o <= 2; o <<= 1) {
        pa0 += __shfl_xor_sync(0xffffffffu, pa0, o);
        pc0 += __shfl_xor_sync(0xffffffffu, pc0, o);
        pa1 += __shfl_xor_sync(0xffffffffu, pa1, o);
        pc1 += __shfl_xor_sync(0xffffffffu, pc1, o);
    }
    if (tq == 0) {
        if (node0 < N) {
            a1[node0] = pa0;
            float d = rsqrtf(fmaxf((float)cnt[node0], 1.0f));
            cd1[node0] = make_float2(pc0, d);
        }
        if (node1 < N) {
            a1[node1] = pa1;
            float d = rsqrtf(fmaxf((float)cnt[node1], 1.0f));
            cd1[node1] = make_float2(pc1, d);
        }
    }
}

// ---------------- edge coefficient precompute (warp per node) ----------------
__global__ void __launch_bounds__(256)
k_coef(const int* __restrict__ csr, const int* __restrict__ cnt,
       const float* __restrict__ a, const float2* __restrict__ cd,
       const float* __restrict__ gbp, int layer,
       __half* __restrict__ ecoef, int N) {
    int warp = (blockIdx.x * blockDim.x + threadIdx.x) >> 5;
    int lane = threadIdx.x & 31;
    if (warp >= N) return;
    int t = warp;
    int deg = min(cnt[t], CSR_CAP);
    float2 cdt = cd[t];
    float base = a[t] + gbp[layer];
    float dt = cdt.y;
    int st = t * CSR_CAP;
    for (int ei = lane; ei < deg; ei += 32) {
        int s = csr[st + ei];
        float2 cs = cd[s];
        float e = tanh_approx(base + cs.x) * dt * cs.y;
        ecoef[st + ei] = __float2half(e);
    }
}

// ---------------- aggregation v4: 4 nodes/warp, precomputed coefs ----------------
// Quarter (8 lanes) owns one dst node; lane owns 8 features (uint4 = 16B).
// Per loop iter: 2 SHFL + 1 LDG.128 + 4 HFMA2 serves 4 edges (one per quarter).
__global__ void __launch_bounds__(256)
k_aggr(const __half* __restrict__ x, const float* __restrict__ raw,
       __half* __restrict__ xn_h,
       const int* __restrict__ csr, const int* __restrict__ cnt,
       const __half* __restrict__ ecoef, const float2* __restrict__ cd,
       const float* __restrict__ gw_next, float* __restrict__ a_next,
       float2* __restrict__ cd_next, int N) {
    int warp = (blockIdx.x * blockDim.x + threadIdx.x) >> 5;
    int lane = threadIdx.x & 31;
    int l = lane & 7;

    int t = warp * 4 + (lane >> 3);
    bool nvalid = (t < N);
    int tc = nvalid ? t : 0;

    int deg = nvalid ? min(cnt[tc], CSR_CAP) : 0;
    int start = tc * CSR_CAP;

    int dm = deg;
    dm = max(dm, __shfl_xor_sync(0xffffffffu, dm, 8));
    dm = max(dm, __shfl_xor_sync(0xffffffffu, dm, 16));

    float acc[8];
    {
        float4 r0 = nvalid ? *(const float4*)(raw + (size_t)t * 64 + l * 8)
                           : make_float4(0.f, 0.f, 0.f, 0.f);
        float4 r1 = nvalid ? *(const float4*)(raw + (size_t)t * 64 + l * 8 + 4)
                           : make_float4(0.f, 0.f, 0.f, 0.f);
        acc[0] = FAGCN_EPS * r0.x; acc[1] = FAGCN_EPS * r0.y;
        acc[2] = FAGCN_EPS * r0.z; acc[3] = FAGCN_EPS * r0.w;
        acc[4] = FAGCN_EPS * r1.x; acc[5] = FAGCN_EPS * r1.y;
        acc[6] = FAGCN_EPS * r1.z; acc[7] = FAGCN_EPS * r1.w;
    }

    for (int b0 = 0; b0 < dm; b0 += 8) {
        int ei = b0 + l;
        int sb = 0;
        unsigned ep = 0;
        if (ei < deg) {
            sb = csr[start + ei];
            __half eh = ecoef[start + ei];
            __half2 e2 = __half2half2(eh);
            ep = *(unsigned*)&e2;
        }
        int mmax = min(8, dm - b0);
        __half2 h0 = __float2half2_rn(0.0f), h1 = h0, h2 = h0, h3 = h0;
        if (mmax == 8) {
#pragma unroll
            for (int bq = 0; bq < 8; bq++) {
                int srcl = (lane & 24) | bq;
                unsigned e = __shfl_sync(0xffffffffu, ep, srcl);
                int s  = __shfl_sync(0xffffffffu, sb, srcl);
                uint4 u = __ldg((const uint4*)(x + (size_t)s * 64 + l * 8));
                h0 = __hfma2(*(__half2*)&u.x, *(__half2*)&e, h0);
                h1 = __hfma2(*(__half2*)&u.y, *(__half2*)&e, h1);
                h2 = __hfma2(*(__half2*)&u.z, *(__half2*)&e, h2);
                h3 = __hfma2(*(__half2*)&u.w, *(__half2*)&e, h3);
            }
        } else {
            for (int bq = 0; bq < mmax; bq++) {
                int srcl = (lane & 24) | bq;
                unsigned e = __shfl_sync(0xffffffffu, ep, srcl);
                int s  = __shfl_sync(0xffffffffu, sb, srcl);
                uint4 u = __ldg((const uint4*)(x + (size_t)s * 64 + l * 8));
                h0 = __hfma2(*(__half2*)&u.x, *(__half2*)&e, h0);
                h1 = __hfma2(*(__half2*)&u.y, *(__half2*)&e, h1);
                h2 = __hfma2(*(__half2*)&u.z, *(__half2*)&e, h2);
                h3 = __hfma2(*(__half2*)&u.w, *(__half2*)&e, h3);
            }
        }
        float2 f0 = __half22float2(h0);
        float2 f1 = __half22float2(h1);
        float2 f2 = __half22float2(h2);
        float2 f3 = __half22float2(h3);
        acc[0] += f0.x; acc[1] += f0.y;
        acc[2] += f1.x; acc[3] += f1.y;
        acc[4] += f2.x; acc[5] += f2.y;
        acc[6] += f3.x; acc[7] += f3.y;
    }

    if (nvalid) {
        __half2 o0 = __floats2half2_rn(acc[0], acc[1]);
        __half2 o1 = __floats2half2_rn(acc[2], acc[3]);
        __half2 o2 = __floats2half2_rn(acc[4], acc[5]);
        __half2 o3 = __floats2half2_rn(acc[6], acc[7]);
        uint4 u;
        u.x = *(unsigned*)&o0; u.y = *(unsigned*)&o1;
        u.z = *(unsigned*)&o2; u.w = *(unsigned*)&o3;
        *(uint4*)(xn_h + (size_t)t * 64 + l * 8) = u;

        // fused next-layer gate precompute
        float4 wa0 = *(const float4*)(gw_next + l * 8);
        float4 wa1 = *(const float4*)(gw_next + l * 8 + 4);
        float4 wc0 = *(const float4*)(gw_next + 64 + l * 8);
        float4 wc1 = *(const float4*)(gw_next + 64 + l * 8 + 4);
        float pa = acc[0]*wa0.x + acc[1]*wa0.y + acc[2]*wa0.z + acc[3]*wa0.w
                 + acc[4]*wa1.x + acc[5]*wa1.y + acc[6]*wa1.z + acc[7]*wa1.w;
        float pc = acc[0]*wc0.x + acc[1]*wc0.y + acc[2]*wc0.z + acc[3]*wc0.w
                 + acc[4]*wc1.x + acc[5]*wc1.y + acc[6]*wc1.z + acc[7]*wc1.w;
#pragma unroll
        for (int o = 4; o; o >>= 1) {
            pa += __shfl_xor_sync(0xffffffffu, pa, o);
            pc += __shfl_xor_sync(0xffffffffu, pc, o);
        }
        if (l == 0) {
            a_next[t] = pa;
            cd_next[t] = make_float2(pc, cd[t].y);
        }
    }
}

// ---------------- aggregation layer 1 + t2 + log_softmax ----------------
__global__ void __launch_bounds__(256)
k_aggr_out(const __half* __restrict__ x, const float* __restrict__ raw,
           const int* __restrict__ csr, const int* __restrict__ cnt,
           const __half* __restrict__ ecoef,
           const float* __restrict__ w2, const float* __restrict__ b2,
           float* __restrict__ out, int N) {
    __shared__ float wS[16 * 64];
    __shared__ float xS[32][68];
    int tx = threadIdx.x;
#pragma unroll
    for (int i = 0; i < 4; i++) wS[tx + i * 256] = w2[tx + i * 256];

    int warp = (blockIdx.x * blockDim.x + tx) >> 5;
    int lane = tx & 31;
    int l = lane & 7;
    int nodeLocal = (tx >> 5) * 4 + (lane >> 3);   // 0..31

    int t = warp * 4 + (lane >> 3);
    bool nvalid = (t < N);
    int tc = nvalid ? t : 0;

    int deg = nvalid ? min(cnt[tc], CSR_CAP) : 0;
    int start = tc * CSR_CAP;

    int dm = deg;
    dm = max(dm, __shfl_xor_sync(0xffffffffu, dm, 8));
    dm = max(dm, __shfl_xor_sync(0xffffffffu, dm, 16));

    float acc[8];
    {
        float4 r0 = nvalid ? *(const float4*)(raw + (size_t)t * 64 + l * 8)
                           : make_float4(0.f, 0.f, 0.f, 0.f);
        float4 r1 = nvalid ? *(const float4*)(raw + (size_t)t * 64 + l * 8 + 4)
                           : make_float4(0.f, 0.f, 0.f, 0.f);
        acc[0] = FAGCN_EPS * r0.x; acc[1] = FAGCN_EPS * r0.y;
        acc[2] = FAGCN_EPS * r0.z; acc[3] = FAGCN_EPS * r0.w;
        acc[4] = FAGCN_EPS * r1.x; acc[5] = FAGCN_EPS * r1.y;
        acc[6] = FAGCN_EPS * r1.z; acc[7] = FAGCN_EPS * r1.w;
    }

    for (int b0 = 0; b0 < dm; b0 += 8) {
        int ei = b0 + l;
        int sb = 0;
        unsigned ep = 0;
        if (ei < deg) {
            sb = csr[start + ei];
            __half eh = ecoef[start + ei];
            __half2 e2 = __half2half2(eh);
            ep = *(unsigned*)&e2;
        }
        int mmax = min(8, dm - b0);
        __half2 h0 = __float2half2_rn(0.0f), h1 = h0, h2 = h0, h3 = h0;
        if (mmax == 8) {
#pragma unroll
            for (int bq = 0; bq < 8; bq++) {
                int srcl = (lane & 24) | bq;
                unsigned e = __shfl_sync(0xffffffffu, ep, srcl);
                int s  = __shfl_sync(0xffffffffu, sb, srcl);
                uint4 u = __ldg((const uint4*)(x + (size_t)s * 64 + l * 8));
                h0 = __hfma2(*(__half2*)&u.x, *(__half2*)&e, h0);
                h1 = __hfma2(*(__half2*)&u.y, *(__half2*)&e, h1);
                h2 = __hfma2(*(__half2*)&u.z, *(__half2*)&e, h2);
                h3 = __hfma2(*(__half2*)&u.w, *(__half2*)&e, h3);
            }
        } else {
            for (int bq = 0; bq < mmax; bq++) {
                int srcl = (lane & 24) | bq;
                unsigned e = __shfl_sync(0xffffffffu, ep, srcl);
                int s  = __shfl_sync(0xffffffffu, sb, srcl);
                uint4 u = __ldg((const uint4*)(x + (size_t)s * 64 + l * 8));
                h0 = __hfma2(*(__half2*)&u.x, *(__half2*)&e, h0);
                h1 = __hfma2(*(__half2*)&u.y, *(__half2*)&e, h1);
                h2 = __hfma2(*(__half2*)&u.z, *(__half2*)&e, h2);
                h3 = __hfma2(*(__half2*)&u.w, *(__half2*)&e, h3);
            }
        }
        float2 f0 = __half22float2(h0);
        float2 f1 = __half22float2(h1);
        float2 f2 = __half22float2(h2);
        float2 f3 = __half22float2(h3);
        acc[0] += f0.x; acc[1] += f0.y;
        acc[2] += f1.x; acc[3] += f1.y;
        acc[4] += f2.x; acc[5] += f2.y;
        acc[6] += f3.x; acc[7] += f3.y;
    }

    *(float4*)(&xS[nodeLocal][l * 8])     = make_float4(acc[0], acc[1], acc[2], acc[3]);
    *(float4*)(&xS[nodeLocal][l * 8 + 4]) = make_float4(acc[4], acc[5], acc[6], acc[7]);
    __syncthreads();

    // t2 GEMV + log_softmax: 32 nodes x 16 outs in 2 passes
#pragma unroll
    for (int p = 0; p < 2; p++) {
        int idx = tx + p * 256;
        int nl2 = idx >> 4;
        int j = idx & 15;
        int node = blockIdx.x * 32 + nl2;
        const float4* xr = (const float4*)(&xS[nl2][0]);
        const float4* wr = (const float4*)(wS + j * 64);
        float logit = b2[j];
#pragma unroll
        for (int k = 0; k < 16; k++) {
            float4 av = xr[k];
            float4 wv = wr[k];
            logit += av.x * wv.x + av.y * wv.y + av.z * wv.z + av.w * wv.w;
        }
        float m = logit;
#pragma unroll
        for (int o = 8; o; o >>= 1) m = fmaxf(m, __shfl_xor_sync(0xffffffffu, m, o));
        float ex = expf(logit - m);
        float s = ex;
#pragma unroll
        for (int o = 8; o; o >>= 1) s += __shfl_xor_sync(0xffffffffu, s, o);
        if (node < N) out[(size_t)node * 16 + j] = logit - m - logf(s);
    }
}

// ---------------- launch ----------------
extern "C" void kernel_launch(void* const* d_in, const int* in_sizes, int n_in,
                              void* d_out, int out_size) {
    const float* h   = (const float*)d_in[0];
    const int*   src = (const int*)  d_in[1];
    const int*   dst = (const int*)  d_in[2];
    const float* t1w = (const float*)d_in[3];
    const float* t1b = (const float*)d_in[4];
    const float* gw  = (const float*)d_in[5];
    const float* gb  = (const float*)d_in[6];
    const float* t2w = (const float*)d_in[7];
    const float* t2b = (const float*)d_in[8];
    float* out = (float*)d_out;

    int N = in_sizes[0] / IN_DIM;
    int E = in_sizes[1];

    float *raw, *a1, *a2;
    __half *raw16, *x1h, *ecoef;
    float2 *cd1, *cd2;
    int *cnt, *csr;
    cudaGetSymbolAddress((void**)&raw,   g_raw);
    cudaGetSymbolAddress((void**)&raw16, g_raw16);
    cudaGetSymbolAddress((void**)&x1h,   g_x1h);
    cudaGetSymbolAddress((void**)&cnt,   g_cnt);
    cudaGetSymbolAddress((void**)&csr,   g_csr);
    cudaGetSymbolAddress((void**)&ecoef, g_ecoef);
    cudaGetSymbolAddress((void**)&a1,    g_a1);
    cudaGetSymbolAddress((void**)&a2,    g_a2);
    cudaGetSymbolAddress((void**)&cd1,   g_cd1);
    cudaGetSymbolAddress((void**)&cd2,   g_cd2);

    // order: zero(1), fill(2), t1(3), coef0(4 <- ncu slot), aggr0(5), coef1(6), aggr_out(7)
    k_zero<<<(N + 255) / 256, 256>>>(cnt, N);
    k_fill<<<(E + 255) / 256, 256>>>(src, dst, cnt, csr, E);

    cudaFuncSetAttribute(k_t1, cudaFuncAttributeMaxDynamicSharedMemorySize, T1_SMEM);
    k_t1<<<(N + T1_BM - 1) / T1_BM, 256, T1_SMEM>>>(h, t1w, t1b, raw, raw16,
                                                    gw, cnt, a1, cd1, N);

    int cblk = (N * 32 + 255) / 256;
    int ablk = (N + 31) / 32;   // 8 warps x 4 nodes per block

    k_coef<<<cblk, 256>>>(csr, cnt, a1, cd1, gb, 0, ecoef, N);
    k_aggr<<<ablk, 256>>>(raw16, raw, x1h, csr, cnt, ecoef, cd1,
                          gw + 128, a2, cd2, N);
    k_coef<<<cblk, 256>>>(csr, cnt, a2, cd2, gb, 1, ecoef, N);
    k_aggr_out<<<ablk, 256>>>(x1h, raw, csr, cnt, ecoef, t2w, t2b, out, N);
}